// round 8
// baseline (speedup 1.0000x reference)
#include <cuda_runtime.h>

#define NB 16
#define ND 512
#define NT_T 4096
#define CD 10
#define CS 1024
#define NTOK (NB*NT_T)

// scratch (device globals — no allocation allowed)
__device__ float g_w[CD*ND];       // w_in[d][D]
__device__ float g_bin[CD];
__device__ float g_lut[ND*CS];     // LUT_T[Do][code]
__device__ float g_orig[CD*NTOK];  // [k][token]
__device__ int   g_idx[NTOK];
__device__ float g_pprob[256*CS];  // per-block avg_prob partials
__device__ float g_pent[256];
__device__ float g_pcom[256];

// ---------------- prep: normalized input weights ----------------
__global__ void prep_in(const float* __restrict__ v, const float* __restrict__ g,
                        const float* __restrict__ bi) {
    int w = threadIdx.x >> 5, l = threadIdx.x & 31;
    if (w >= CD) return;
    float s = 0.f;
    for (int i = l; i < ND; i += 32) { float t = v[w*ND + i]; s += t*t; }
    #pragma unroll
    for (int o = 16; o; o >>= 1) s += __shfl_xor_sync(0xffffffffu, s, o);
    float sc = g[w] * rsqrtf(s);
    for (int i = l; i < ND; i += 32) g_w[w*ND + i] = v[w*ND + i] * sc;
    if (l == 0) g_bin[w] = bi[w];
}

// ---------------- prep: output LUT (all 1024 sign patterns) ----------------
__global__ void prep_lut(const float* __restrict__ v, const float* __restrict__ g,
                         const float* __restrict__ bo) {
    int Do = blockIdx.x;
    __shared__ float w[CD];
    __shared__ float bb;
    if (threadIdx.x == 0) {
        float tv[CD]; float s = 0.f;
        #pragma unroll
        for (int k = 0; k < CD; k++) { tv[k] = v[Do*CD + k]; s += tv[k]*tv[k]; }
        float sc = g[Do] * rsqrtf(s);
        #pragma unroll
        for (int k = 0; k < CD; k++) w[k] = tv[k] * sc;
        bb = bo[Do];
    }
    __syncthreads();
    for (int j = threadIdx.x; j < CS; j += blockDim.x) {
        float s = bb;
        #pragma unroll
        for (int k = 0; k < CD; k++)
            s += ((j >> (9 - k)) & 1) ? w[k] : -w[k];
        g_lut[Do*CS + j] = s;
    }
}

// ---------------- projection: orig[k][token], indices ----------------
__global__ void __launch_bounds__(256) proj(const float* __restrict__ x,
                                            float* __restrict__ idxF) {
    __shared__ float wsh[ND*CD];
    for (int i = threadIdx.x; i < ND*CD; i += 256) {
        int Dc = i / CD, k = i - Dc*CD;
        wsh[i] = g_w[k*ND + Dc];
    }
    __syncthreads();
    int b = blockIdx.x >> 4;
    int t = ((blockIdx.x & 15) << 8) + threadIdx.x;
    const float* xp = x + (size_t)b * ND * NT_T + t;
    float acc[CD];
    #pragma unroll
    for (int k = 0; k < CD; k++) acc[k] = g_bin[k];
    #pragma unroll 4
    for (int Dc = 0; Dc < ND; Dc++) {
        float xv = xp[(size_t)Dc * NT_T];
        #pragma unroll
        for (int k = 0; k < CD; k++) acc[k] = fmaf(xv, wsh[Dc*CD + k], acc[k]);
    }
    int gt = b*NT_T + t;
    int idx = 0;
    #pragma unroll
    for (int k = 0; k < CD; k++) {
        g_orig[k*NTOK + gt] = acc[k];
        idx |= (int)(acc[k] > 0.f) << (9 - k);
    }
    g_idx[gt] = idx;
    idxF[gt] = (float)idx;
}

// ---------------- softmax / entropy / commit ----------------
__global__ void __launch_bounds__(256) entk() {
    __shared__ float sprob[CS];
    __shared__ float sred[16];
    for (int i = threadIdx.x; i < CS; i += 256) sprob[i] = 0.f;
    __syncthreads();

    int w = threadIdx.x >> 5, l = threadIdx.x & 31;
    float accp[32];
    #pragma unroll
    for (int h = 0; h < 32; h++) accp[h] = 0.f;
    float hent = 0.f, hcom = 0.f;
    int base = blockIdx.x * 256 + w * 32;

    for (int i = 0; i < 32; i++) {
        int gt = base + i;
        float ov[CD]; float m = 0.f;
        #pragma unroll
        for (int k = 0; k < CD; k++) { ov[k] = g_orig[k*NTOK + gt]; m += fabsf(ov[k]); }
        // lane l: lo over dims 5..9 (bits 4..0 of code); hi over dims 0..4 (bits 9..5)
        float hi = 0.f, lo = 0.f;
        #pragma unroll
        for (int k = 0; k < 5; k++) hi += ((l >> (4 - k)) & 1) ? ov[k] : -ov[k];
        #pragma unroll
        for (int k = 5; k < CD; k++) lo += ((l >> (9 - k)) & 1) ? ov[k] : -ov[k];

        float e[32]; float z = 0.f;
        #pragma unroll
        for (int h = 0; h < 32; h++) {
            float hv = __shfl_sync(0xffffffffu, hi, h);
            float a = 200.f * (hv + lo - m);
            float ee = __expf(a);
            e[h] = ee; z += ee;
        }
        #pragma unroll
        for (int o = 16; o; o >>= 1) z += __shfl_xor_sync(0xffffffffu, z, o);
        float invZ = 1.f / z;
        float logZ = __logf(z);
        #pragma unroll
        for (int h = 0; h < 32; h++) {
            float hv = __shfl_sync(0xffffffffu, hi, h);
            float a = 200.f * (hv + lo - m);       // = log e[h]
            float p = e[h] * invZ;
            float lp = (p >= 1e-5f) ? (a - logZ) : -11.512925465f;
            hent -= p * lp;
            accp[h] += p;
        }
        float c = 0.f;
        #pragma unroll
        for (int k = 0; k < CD; k++) { float q = fabsf(ov[k]) - 1.f; c += q*q; }
        hcom += c;  // identical across lanes (uniform token)
    }

    // lane l owns code j = h*32 + l: conflict-free shared atomics across warps
    #pragma unroll
    for (int h = 0; h < 32; h++) atomicAdd(&sprob[h*32 + l], accp[h]);

    #pragma unroll
    for (int o = 16; o; o >>= 1) hent += __shfl_xor_sync(0xffffffffu, hent, o);
    if (l == 0) { sred[w] = hent; sred[8 + w] = hcom; }
    __syncthreads();
    if (threadIdx.x == 0) {
        float se = 0.f, sc = 0.f;
        #pragma unroll
        for (int ww = 0; ww < 8; ww++) { se += sred[ww]; sc += sred[8 + ww]; }
        g_pent[blockIdx.x] = se;
        g_pcom[blockIdx.x] = sc;
    }
    for (int i = threadIdx.x; i < CS; i += 256)
        g_pprob[blockIdx.x*CS + i] = sprob[i];
}

// ---------------- final reduction -> aux loss ----------------
__global__ void __launch_bounds__(1024) fin(float* __restrict__ aux) {
    __shared__ float red[96];
    int tid = threadIdx.x, lane = tid & 31, warp = tid >> 5;
    float s = 0.f;
    for (int blk = 0; blk < 256; blk++) s += g_pprob[blk*CS + tid];
    float avg = s * (1.0f / NTOK);
    float term = -avg * __logf(fmaxf(avg, 1e-5f));
    float entp = (tid < 256) ? g_pent[tid] : 0.f;
    float comp = (tid < 256) ? g_pcom[tid] : 0.f;
    #pragma unroll
    for (int o = 16; o; o >>= 1) {
        term += __shfl_xor_sync(0xffffffffu, term, o);
        entp += __shfl_xor_sync(0xffffffffu, entp, o);
        comp += __shfl_xor_sync(0xffffffffu, comp, o);
    }
    if (lane == 0) { red[warp] = term; red[32 + warp] = entp; red[64 + warp] = comp; }
    __syncthreads();
    if (tid < 32) {
        float a = red[tid], b2 = red[32 + tid], c2 = red[64 + tid];
        #pragma unroll
        for (int o = 16; o; o >>= 1) {
            a  += __shfl_xor_sync(0xffffffffu, a,  o);
            b2 += __shfl_xor_sync(0xffffffffu, b2, o);
            c2 += __shfl_xor_sync(0xffffffffu, c2, o);
        }
        if (tid == 0) {
            float ce = a;
            float pse = b2 * (1.0f / NTOK);
            float commit = c2 * (1.0f / (NTOK * CD));
            aux[0] = pse - ce + commit;
        }
    }
}

// ---------------- output: pure LUT gather ----------------
__global__ void __launch_bounds__(128) gatherk(float* __restrict__ out) {
    int b = blockIdx.z, Do = blockIdx.y;
    int t = (blockIdx.x * 128 + threadIdx.x) * 4;
    int4 iv = *(const int4*)&g_idx[b*NT_T + t];
    const float* row = &g_lut[Do*CS];
    float4 o;
    o.x = __ldg(&row[iv.x]);
    o.y = __ldg(&row[iv.y]);
    o.z = __ldg(&row[iv.z]);
    o.w = __ldg(&row[iv.w]);
    *(float4*)&out[((size_t)(b*ND + Do)) * NT_T + t] = o;
}

extern "C" void kernel_launch(void* const* d_in, const int* in_sizes, int n_in,
                              void* d_out, int out_size) {
    const float* x     = (const float*)d_in[0];
    const float* in_v  = (const float*)d_in[1];
    const float* in_g  = (const float*)d_in[2];
    const float* in_b  = (const float*)d_in[3];
    const float* out_v = (const float*)d_in[4];
    const float* out_g = (const float*)d_in[5];
    const float* out_b = (const float*)d_in[6];

    float* out  = (float*)d_out;
    float* idxF = out + (size_t)NB * ND * NT_T;
    float* aux  = idxF + NTOK;

    prep_in<<<1, 320>>>(in_v, in_g, in_b);
    prep_lut<<<ND, 256>>>(out_v, out_g, out_b);
    proj<<<256, 256>>>(x, idxF);
    entk<<<256, 256>>>();
    fin<<<1, 1024>>>(aux);
    gatherk<<<dim3(NT_T/512, ND, NB), 128>>>(out);
}

// round 9
// speedup vs baseline: 1.1254x; 1.1254x over previous
#include <cuda_runtime.h>

#define NB 16
#define ND 512
#define NT_T 4096
#define CD 10
#define CS 1024
#define NTOK (NB*NT_T)

// scratch (device globals — no allocation allowed)
__device__ float g_w[CD*ND];       // w_in[d][D]
__device__ float g_bin[CD];
__device__ float g_lut[ND*CS];     // LUT_T[Do][code]
__device__ float g_orig[CD*NTOK];  // [k][token]
__device__ int   g_idx[NTOK];
__device__ float g_pprob[256*CS];  // per-block avg_prob partials
__device__ float g_pent[256];
__device__ float g_pcom[256];

// ---------------- prep: normalized input weights ----------------
__global__ void prep_in(const float* __restrict__ v, const float* __restrict__ g,
                        const float* __restrict__ bi) {
    int w = threadIdx.x >> 5, l = threadIdx.x & 31;
    if (w >= CD) return;
    float s = 0.f;
    for (int i = l; i < ND; i += 32) { float t = v[w*ND + i]; s += t*t; }
    #pragma unroll
    for (int o = 16; o; o >>= 1) s += __shfl_xor_sync(0xffffffffu, s, o);
    float sc = g[w] * rsqrtf(s);
    for (int i = l; i < ND; i += 32) g_w[w*ND + i] = v[w*ND + i] * sc;
    if (l == 0) g_bin[w] = bi[w];
}

// ---------------- prep: output LUT (all 1024 sign patterns) ----------------
__global__ void prep_lut(const float* __restrict__ v, const float* __restrict__ g,
                         const float* __restrict__ bo) {
    int Do = blockIdx.x;
    __shared__ float w[CD];
    __shared__ float bb;
    if (threadIdx.x == 0) {
        float tv[CD]; float s = 0.f;
        #pragma unroll
        for (int k = 0; k < CD; k++) { tv[k] = v[Do*CD + k]; s += tv[k]*tv[k]; }
        float sc = g[Do] * rsqrtf(s);
        #pragma unroll
        for (int k = 0; k < CD; k++) w[k] = tv[k] * sc;
        bb = bo[Do];
    }
    __syncthreads();
    for (int j = threadIdx.x; j < CS; j += blockDim.x) {
        float s = bb;
        #pragma unroll
        for (int k = 0; k < CD; k++)
            s += ((j >> (9 - k)) & 1) ? w[k] : -w[k];
        g_lut[Do*CS + j] = s;
    }
}

// ---------------- projection: orig[k][token], indices ----------------
__global__ void __launch_bounds__(256) proj(const float* __restrict__ x,
                                            float* __restrict__ idxF) {
    __shared__ float wsh[ND*CD];
    for (int i = threadIdx.x; i < ND*CD; i += 256) {
        int Dc = i / CD, k = i - Dc*CD;
        wsh[i] = g_w[k*ND + Dc];
    }
    __syncthreads();
    int b = blockIdx.x >> 4;
    int t = ((blockIdx.x & 15) << 8) + threadIdx.x;
    const float* xp = x + (size_t)b * ND * NT_T + t;
    float acc[CD];
    #pragma unroll
    for (int k = 0; k < CD; k++) acc[k] = g_bin[k];
    #pragma unroll 4
    for (int Dc = 0; Dc < ND; Dc++) {
        float xv = xp[(size_t)Dc * NT_T];
        #pragma unroll
        for (int k = 0; k < CD; k++) acc[k] = fmaf(xv, wsh[Dc*CD + k], acc[k]);
    }
    int gt = b*NT_T + t;
    int idx = 0;
    #pragma unroll
    for (int k = 0; k < CD; k++) {
        g_orig[k*NTOK + gt] = acc[k];
        idx |= (int)(acc[k] > 0.f) << (9 - k);
    }
    g_idx[gt] = idx;
    idxF[gt] = (float)idx;
}

// ---------------- softmax / entropy / commit ----------------
// Per token: logits a_j = 200*(hi_h + lo_l - m), m = sum|ov| (analytic max, a<=0).
// entropy = logZ - (1/Z) * sum_j e_j * a_j   (exact where clip inactive; at
// inv_temp=100 all sub-threshold codes underflow to e=0, contributing 0).
// Work in log2 domain: a2 = 200*log2(e)*(hi+lo-m); e = exp2(a2); ln-scale once.
#define L2E200 288.5390082f      /* 200 * log2(e) */
#define LN2F   0.6931471806f
__global__ void __launch_bounds__(256) entk() {
    __shared__ float sprob[CS];
    __shared__ float sred[16];
    for (int i = threadIdx.x; i < CS; i += 256) sprob[i] = 0.f;
    __syncthreads();

    int w = threadIdx.x >> 5, l = threadIdx.x & 31;
    float accp[32];
    #pragma unroll
    for (int h = 0; h < 32; h++) accp[h] = 0.f;
    float hent = 0.f, hcom = 0.f;   // lane-uniform accumulators
    int base = blockIdx.x * 256 + w * 32;

    for (int i = 0; i < 32; i++) {
        int gt = base + i;
        float ov[CD]; float m = 0.f;
        #pragma unroll
        for (int k = 0; k < CD; k++) { ov[k] = g_orig[k*NTOK + gt]; m += fabsf(ov[k]); }
        // lane l: lo over dims 5..9 (code bits 4..0); hi over dims 0..4 (bits 9..5)
        float hi = 0.f, lo = 0.f;
        #pragma unroll
        for (int k = 0; k < 5; k++) hi += ((l >> (4 - k)) & 1) ? ov[k] : -ov[k];
        #pragma unroll
        for (int k = 5; k < CD; k++) lo += ((l >> (9 - k)) & 1) ? ov[k] : -ov[k];
        float c0 = L2E200 * (lo - m);   // a2 = fma(L2E200, hv, c0)

        float e[32]; float zp = 0.f, sp = 0.f;
        #pragma unroll
        for (int h = 0; h < 32; h++) {
            float hv = __shfl_sync(0xffffffffu, hi, h);
            float a2 = fmaf(L2E200, hv, c0);
            float ee = exp2f(a2);
            e[h] = ee;
            zp += ee;
            sp = fmaf(ee, a2, sp);
        }
        #pragma unroll
        for (int o = 16; o; o >>= 1) {
            zp += __shfl_xor_sync(0xffffffffu, zp, o);
            sp += __shfl_xor_sync(0xffffffffu, sp, o);
        }
        float invZ = 1.f / zp;
        // entropy (nat) = ln2 * (log2(z) - sp/z)
        hent += LN2F * (__log2f(zp) - sp * invZ);
        #pragma unroll
        for (int h = 0; h < 32; h++) accp[h] = fmaf(e[h], invZ, accp[h]);

        float c = 0.f;
        #pragma unroll
        for (int k = 0; k < CD; k++) { float q = fabsf(ov[k]) - 1.f; c += q*q; }
        hcom += c;  // identical across lanes (uniform token)
    }

    // lane l owns code j = h*32 + l: conflict-free shared atomics across warps
    #pragma unroll
    for (int h = 0; h < 32; h++) atomicAdd(&sprob[h*32 + l], accp[h]);

    if (l == 0) { sred[w] = hent; sred[8 + w] = hcom; }   // lane-uniform: no reduce
    __syncthreads();
    if (threadIdx.x == 0) {
        float se = 0.f, sc = 0.f;
        #pragma unroll
        for (int ww = 0; ww < 8; ww++) { se += sred[ww]; sc += sred[8 + ww]; }
        g_pent[blockIdx.x] = se;
        g_pcom[blockIdx.x] = sc;
    }
    for (int i = threadIdx.x; i < CS; i += 256)
        g_pprob[blockIdx.x*CS + i] = sprob[i];
}

// ---------------- final reduction -> aux loss ----------------
__global__ void __launch_bounds__(1024) fin(float* __restrict__ aux) {
    __shared__ float red[96];
    int tid = threadIdx.x, lane = tid & 31, warp = tid >> 5;
    float s = 0.f;
    for (int blk = 0; blk < 256; blk++) s += g_pprob[blk*CS + tid];
    float avg = s * (1.0f / NTOK);
    float term = -avg * __logf(fmaxf(avg, 1e-5f));
    float entp = (tid < 256) ? g_pent[tid] : 0.f;
    float comp = (tid < 256) ? g_pcom[tid] : 0.f;
    #pragma unroll
    for (int o = 16; o; o >>= 1) {
        term += __shfl_xor_sync(0xffffffffu, term, o);
        entp += __shfl_xor_sync(0xffffffffu, entp, o);
        comp += __shfl_xor_sync(0xffffffffu, comp, o);
    }
    if (lane == 0) { red[warp] = term; red[32 + warp] = entp; red[64 + warp] = comp; }
    __syncthreads();
    if (tid < 32) {
        float a = red[tid], b2 = red[32 + tid], c2 = red[64 + tid];
        #pragma unroll
        for (int o = 16; o; o >>= 1) {
            a  += __shfl_xor_sync(0xffffffffu, a,  o);
            b2 += __shfl_xor_sync(0xffffffffu, b2, o);
            c2 += __shfl_xor_sync(0xffffffffu, c2, o);
        }
        if (tid == 0) {
            float ce = a;
            float pse = b2 * (1.0f / NTOK);
            float commit = c2 * (1.0f / (NTOK * CD));
            aux[0] = pse - ce + commit;
        }
    }
}

// ---------------- output: pure LUT gather ----------------
__global__ void __launch_bounds__(128) gatherk(float* __restrict__ out) {
    int b = blockIdx.z, Do = blockIdx.y;
    int t = (blockIdx.x * 128 + threadIdx.x) * 4;
    int4 iv = *(const int4*)&g_idx[b*NT_T + t];
    const float* row = &g_lut[Do*CS];
    float4 o;
    o.x = __ldg(&row[iv.x]);
    o.y = __ldg(&row[iv.y]);
    o.z = __ldg(&row[iv.z]);
    o.w = __ldg(&row[iv.w]);
    *(float4*)&out[((size_t)(b*ND + Do)) * NT_T + t] = o;
}

extern "C" void kernel_launch(void* const* d_in, const int* in_sizes, int n_in,
                              void* d_out, int out_size) {
    const float* x     = (const float*)d_in[0];
    const float* in_v  = (const float*)d_in[1];
    const float* in_g  = (const float*)d_in[2];
    const float* in_b  = (const float*)d_in[3];
    const float* out_v = (const float*)d_in[4];
    const float* out_g = (const float*)d_in[5];
    const float* out_b = (const float*)d_in[6];

    float* out  = (float*)d_out;
    float* idxF = out + (size_t)NB * ND * NT_T;
    float* aux  = idxF + NTOK;

    prep_in<<<1, 320>>>(in_v, in_g, in_b);
    prep_lut<<<ND, 256>>>(out_v, out_g, out_b);
    proj<<<256, 256>>>(x, idxF);
    entk<<<256, 256>>>();
    fin<<<1, 1024>>>(aux);
    gatherk<<<dim3(NT_T/512, ND, NB), 128>>>(out);
}

// round 13
// speedup vs baseline: 1.1373x; 1.0106x over previous
#include <cuda_runtime.h>

#define NB 16
#define ND 512
#define NT_T 4096
#define CD 10
#define CS 1024
#define NTOK (NB*NT_T)
#define EBLK 512
#define GTOK 16
#define L2E200 288.5390082f      /* 200 * log2(e) */
#define LN2F   0.6931471806f

// scratch (device globals — no allocation allowed)
__device__ float g_w[CD*ND];        // w_in[k][D]
__device__ float g_bin[CD];
__device__ float g_wo[ND*CD];       // normalized out weights [Do][k]
__device__ float g_bo2[ND];
__device__ float g_lutT[CS*ND];     // LUT transposed: [code][Do]
__device__ float g_orig[CD*NTOK];   // [k][token]
__device__ int   g_idx[NTOK];
__device__ float g_pprob[EBLK*CS];
__device__ float g_pent[EBLK];
__device__ float g_pcom[EBLK];
__device__ float g_term[CS];

// ---------------- prep: normalized input weights ----------------
__global__ void prep_in(const float* __restrict__ v, const float* __restrict__ g,
                        const float* __restrict__ bi) {
    int w = threadIdx.x >> 5, l = threadIdx.x & 31;
    if (w >= CD) return;
    float s = 0.f;
    for (int i = l; i < ND; i += 32) { float t = v[w*ND + i]; s += t*t; }
    #pragma unroll
    for (int o = 16; o; o >>= 1) s += __shfl_xor_sync(0xffffffffu, s, o);
    float sc = g[w] * rsqrtf(s);
    for (int i = l; i < ND; i += 32) g_w[w*ND + i] = v[w*ND + i] * sc;
    if (l == 0) g_bin[w] = bi[w];
}

// ---------------- prep: normalized output weights ----------------
__global__ void prep_out(const float* __restrict__ v, const float* __restrict__ g,
                         const float* __restrict__ bo) {
    int Do = blockIdx.x * blockDim.x + threadIdx.x;
    if (Do >= ND) return;
    float tv[CD]; float s = 0.f;
    #pragma unroll
    for (int k = 0; k < CD; k++) { tv[k] = v[Do*CD + k]; s += tv[k]*tv[k]; }
    float sc = g[Do] * rsqrtf(s);
    #pragma unroll
    for (int k = 0; k < CD; k++) g_wo[Do*CD + k] = tv[k] * sc;
    g_bo2[Do] = bo[Do];
}

// ---------------- prep: transposed LUT [code][Do] ----------------
__global__ void prep_lutT() {
    int j = blockIdx.x;
    for (int Do = threadIdx.x; Do < ND; Do += 128) {
        float s = g_bo2[Do];
        #pragma unroll
        for (int k = 0; k < CD; k++)
            s += ((j >> (9 - k)) & 1) ? g_wo[Do*CD + k] : -g_wo[Do*CD + k];
        g_lutT[j*ND + Do] = s;
    }
}

// ---------------- projection: orig[k][token], indices ----------------
__global__ void __launch_bounds__(256) proj(const float* __restrict__ x,
                                            float* __restrict__ idxF) {
    __shared__ float wsh[ND*12];   // padded to 12 floats/row for LDS.128
    for (int i = threadIdx.x; i < ND*12; i += 256) {
        int Dc = i / 12, k = i - Dc*12;
        wsh[i] = (k < CD) ? g_w[k*ND + Dc] : 0.f;
    }
    __syncthreads();
    int b = blockIdx.x >> 4;
    int t = ((blockIdx.x & 15) << 8) + threadIdx.x;
    const float* xp = x + (size_t)b * ND * NT_T + t;
    float acc[CD];
    #pragma unroll
    for (int k = 0; k < CD; k++) acc[k] = g_bin[k];
    const float4* wv = (const float4*)wsh;
    #pragma unroll 4
    for (int Dc = 0; Dc < ND; Dc++) {
        float xv = xp[(size_t)Dc * NT_T];
        float4 w0 = wv[Dc*3], w1 = wv[Dc*3+1], w2 = wv[Dc*3+2];
        acc[0] = fmaf(xv, w0.x, acc[0]); acc[1] = fmaf(xv, w0.y, acc[1]);
        acc[2] = fmaf(xv, w0.z, acc[2]); acc[3] = fmaf(xv, w0.w, acc[3]);
        acc[4] = fmaf(xv, w1.x, acc[4]); acc[5] = fmaf(xv, w1.y, acc[5]);
        acc[6] = fmaf(xv, w1.z, acc[6]); acc[7] = fmaf(xv, w1.w, acc[7]);
        acc[8] = fmaf(xv, w2.x, acc[8]); acc[9] = fmaf(xv, w2.y, acc[9]);
    }
    int gt = b*NT_T + t;
    int idx = 0;
    #pragma unroll
    for (int k = 0; k < CD; k++) {
        g_orig[k*NTOK + gt] = acc[k];
        idx |= (int)(acc[k] > 0.f) << (9 - k);
    }
    g_idx[gt] = idx;
    idxF[gt] = (float)idx;
}

// ---------------- softmax / entropy / commit (factorized exp) ----------------
// e_{h,l} = exp2(a(hi_h-mhi)) * exp2(a(lo_l-mlo));  Z = S*SL;
// sum e*a2 = SL*U + S*V  with U = sum ehi*phi, V = sum elo*plo.
__global__ void __launch_bounds__(256) entk() {
    __shared__ float sprob[CS];
    __shared__ float sred[16];
    for (int i = threadIdx.x; i < CS; i += 256) sprob[i] = 0.f;
    __syncthreads();

    int w = threadIdx.x >> 5, l = threadIdx.x & 31;
    float accp[32];
    #pragma unroll
    for (int h = 0; h < 32; h++) accp[h] = 0.f;
    float hent = 0.f, hcom = 0.f;     // lane-uniform
    int base = blockIdx.x * 128 + w * 16;

    for (int i = 0; i < 16; i++) {
        int gt = base + i;
        float ov[CD], aov[CD];
        #pragma unroll
        for (int k = 0; k < CD; k++) { ov[k] = g_orig[k*NTOK + gt]; aov[k] = fabsf(ov[k]); }
        float mhi = aov[0]+aov[1]+aov[2]+aov[3]+aov[4];
        float mlo = aov[5]+aov[6]+aov[7]+aov[8]+aov[9];
        // lane l: hi uses dims 0..4 (code bits 9..5), lo uses dims 5..9 (bits 4..0)
        float hi = 0.f, lo = 0.f;
        #pragma unroll
        for (int k = 0; k < 5; k++) hi += ((l >> (4 - k)) & 1) ? ov[k] : -ov[k];
        #pragma unroll
        for (int k = 5; k < CD; k++) lo += ((l >> (9 - k)) & 1) ? ov[k] : -ov[k];
        float phi = L2E200 * (hi - mhi);     // <= 0
        float plo = L2E200 * (lo - mlo);     // <= 0
        float ehi = exp2f(phi);
        float elo = exp2f(plo);
        float r1 = ehi, r2 = ehi * phi, r3 = elo, r4 = elo * plo;
        #pragma unroll
        for (int o = 16; o; o >>= 1) {
            r1 += __shfl_xor_sync(0xffffffffu, r1, o);
            r2 += __shfl_xor_sync(0xffffffffu, r2, o);
            r3 += __shfl_xor_sync(0xffffffffu, r3, o);
            r4 += __shfl_xor_sync(0xffffffffu, r4, o);
        }
        float Z = r1 * r3;                   // >= 1 (argmax factors are 1)
        float invZ = 1.f / Z;
        hent += LN2F * (__log2f(Z) - (r3*r2 + r1*r4) * invZ);
        float wgt = elo * invZ;
        #pragma unroll
        for (int h = 0; h < 32; h++)
            accp[h] = fmaf(__shfl_sync(0xffffffffu, ehi, h), wgt, accp[h]);
        #pragma unroll
        for (int k = 0; k < CD; k++) { float q = aov[k] - 1.f; hcom = fmaf(q, q, hcom); }
    }

    // lane l owns code j = h*32 + l: conflict-free shared atomics across warps
    #pragma unroll
    for (int h = 0; h < 32; h++) atomicAdd(&sprob[h*32 + l], accp[h]);

    if (l == 0) { sred[w] = hent; sred[8 + w] = hcom; }
    __syncthreads();
    if (threadIdx.x == 0) {
        float se = 0.f, sc = 0.f;
        #pragma unroll
        for (int ww = 0; ww < 8; ww++) { se += sred[ww]; sc += sred[8 + ww]; }
        g_pent[blockIdx.x] = se;
        g_pcom[blockIdx.x] = sc;
    }
    for (int i = threadIdx.x; i < CS; i += 256)
        g_pprob[blockIdx.x*CS + i] = sprob[i];
}

// ---------------- final reduction A: avg_prob -> per-code term ----------------
__global__ void finA() {
    int code = blockIdx.x * 128 + threadIdx.x;
    float s = 0.f;
    #pragma unroll 8
    for (int blk = 0; blk < EBLK; blk++) s += g_pprob[blk*CS + code];
    float avg = s * (1.0f / NTOK);
    g_term[code] = -avg * __logf(fmaxf(avg, 1e-5f));
}

// ---------------- final reduction B -> aux loss ----------------
__global__ void __launch_bounds__(1024) finB(float* __restrict__ aux) {
    __shared__ float red[96];
    int tid = threadIdx.x, lane = tid & 31, warp = tid >> 5;
    float term = g_term[tid];
    float entp = (tid < EBLK) ? g_pent[tid] : 0.f;
    float comp = (tid < EBLK) ? g_pcom[tid] : 0.f;
    #pragma unroll
    for (int o = 16; o; o >>= 1) {
        term += __shfl_xor_sync(0xffffffffu, term, o);
        entp += __shfl_xor_sync(0xffffffffu, entp, o);
        comp += __shfl_xor_sync(0xffffffffu, comp, o);
    }
    if (lane == 0) { red[warp] = term; red[32 + warp] = entp; red[64 + warp] = comp; }
    __syncthreads();
    if (tid < 32) {
        float a = red[tid], b2 = red[32 + tid], c2 = red[64 + tid];
        #pragma unroll
        for (int o = 16; o; o >>= 1) {
            a  += __shfl_xor_sync(0xffffffffu, a,  o);
            b2 += __shfl_xor_sync(0xffffffffu, b2, o);
            c2 += __shfl_xor_sync(0xffffffffu, c2, o);
        }
        if (tid == 0) {
            float ce = a;
            float pse = b2 * (1.0f / NTOK);
            float commit = c2 * (1.0f / (NTOK * CD));
            aux[0] = pse - ce + commit;
        }
    }
}

// ---------------- output: smem-staged LUT gather ----------------
// Block: 16 tokens x all 512 Do. Phase 1: coalesced-load 16 lutT rows (2KB each)
// into shared. Phase 2: fully-sectored 64B stores, random access stays in LDS.
__global__ void __launch_bounds__(256) gatherk2(float* __restrict__ out) {
    __shared__ float sm[GTOK][513];   // +1 pad: conflict-light reads
    __shared__ int sidx[GTOK];
    int blk = blockIdx.x;
    int b = blk >> 8;                 // NT_T/GTOK = 256 chunks per b
    int t0 = (blk & 255) * GTOK;
    if (threadIdx.x < GTOK) sidx[threadIdx.x] = g_idx[b*NT_T + t0 + threadIdx.x];
    __syncthreads();
    {
        int r = threadIdx.x >> 4;     // 16 threads per row
        int c = threadIdx.x & 15;
        const float* row = &g_lutT[(size_t)sidx[r] * ND];
        #pragma unroll
        for (int j = 0; j < 32; j++)
            sm[r][c + j*16] = row[c + j*16];
    }
    __syncthreads();
    int wrp = threadIdx.x >> 5, l = threadIdx.x & 31;
    int tok = l & 15, d2 = l >> 4;
    size_t obase = (size_t)b * ND * NT_T + t0 + tok;
    #pragma unroll 8
    for (int it = 0; it < 32; it++) {
        int Do = wrp*64 + it*2 + d2;
        out[obase + (size_t)Do * NT_T] = sm[tok][Do];
    }
}

extern "C" void kernel_launch(void* const* d_in, const int* in_sizes, int n_in,
                              void* d_out, int out_size) {
    const float* x     = (const float*)d_in[0];
    const float* in_v  = (const float*)d_in[1];
    const float* in_g  = (const float*)d_in[2];
    const float* in_b  = (const float*)d_in[3];
    const float* out_v = (const float*)d_in[4];
    const float* out_g = (const float*)d_in[5];
    const float* out_b = (const float*)d_in[6];

    float* out  = (float*)d_out;
    float* idxF = out + (size_t)NB * ND * NT_T;
    float* aux  = idxF + NTOK;

    prep_in<<<1, 320>>>(in_v, in_g, in_b);
    prep_out<<<2, 256>>>(out_v, out_g, out_b);
    prep_lutT<<<CS, 128>>>();
    proj<<<256, 256>>>(x, idxF);
    entk<<<EBLK, 256>>>();
    finA<<<8, 128>>>();
    finB<<<1, 1024>>>(aux);
    gatherk2<<<NTOK/GTOK, 256>>>(out);
}